// round 16
// baseline (speedup 1.0000x reference)
#include <cuda_runtime.h>
#include <cuda_bf16.h>
#include <stdint.h>

// ---------------------------------------------------------------------------
// MultiHeadAttention: out = LN(ctx@W_fc + X@W_fc0), attn materialized.
// B=8, S=2048, D=128, H=4, dk=dv=32.
// Output layout: [out (8*2048*128)] then [attn (8*4*2048*2048)].
// R16: K/V fragment loads via ldmatrix.m8n8.x4 (96 LDS.32 -> 24 LDSM per
// chunk per thread in attn; 32 -> 8 in rowsum). Frag mapping: non-trans
// ldmatrix with row addresses == the exact uint32 pattern used before.
// ---------------------------------------------------------------------------

namespace {
constexpr int BATCH = 8;
constexpr int SEQ   = 2048;
constexpr int DM    = 128;
constexpr int NR    = BATCH * SEQ;                 // 16384 rows
constexpr size_t OUT_ELEMS = (size_t)NR * DM;      // 2,097,152
constexpr int TQ = 128;                            // q-tile per block
constexpr int TK = 64;                             // k-chunk
constexpr int NC = SEQ / TK;                       // 32 chunks
constexpr int SW = SEQ / 32;                       // 64 mask words per row

// attn_mma smem (bf16 units) + mask word region
constexpr int QSTR = 40;
constexpr int ESTR = 72;
constexpr int BUF_SZ  = 64 * QSTR * 2 + 32 * ESTR;     // 7424 bf16
constexpr int SMEM_BF16 = 3 * BUF_SZ;                  // 22272
constexpr size_t MW_BYTES = 3 * 128 * 2 * 4;           // 3072 B
constexpr size_t SMEM_BYTES = (size_t)SMEM_BF16 * 2 + MW_BYTES;  // 47,616 B

// rowsum_pass smem
constexpr int KBUF = 64 * QSTR;                        // 2560 bf16
constexpr size_t RS_SMEM_BYTES = (size_t)(3 * KBUF) * 2 + MW_BYTES;  // 18,432 B

// proj_tc / out_ln_tc smem
constexpr int PSTR = 72;
constexpr int PA_H = 0;
constexpr int PA_L = PA_H + 64 * PSTR;
constexpr int PW_H = PA_L + 64 * PSTR;
constexpr int PW_L = PW_H + 128 * PSTR;
constexpr int P_BF16 = PW_L + 128 * PSTR;
constexpr size_t P_SMEM_BYTES = (size_t)P_BF16 * 2;    // 55,296 B
constexpr int VSTR = 136;
}

// Scratch (device globals: allocation-free rule)
__device__ float g_R  [NR * DM];
__device__ float g_rinv[BATCH * 4 * SEQ];
__device__ uint32_t g_mbits[(size_t)BATCH * SEQ * SW];   // 4 MB bit mask
__device__ __nv_bfloat16 g_Xh[3 * NR * DM];
__device__ __nv_bfloat16 g_Xl[3 * NR * DM];
__device__ __nv_bfloat16 g_Wth[5 * DM * DM];
__device__ __nv_bfloat16 g_Wtl[5 * DM * DM];
__device__ __nv_bfloat16 g_Qh[NR * DM];
__device__ __nv_bfloat16 g_Ql[NR * DM];
__device__ __nv_bfloat16 g_Kh[NR * DM];
__device__ __nv_bfloat16 g_Kl[NR * DM];
__device__ __nv_bfloat16 g_Ch[NR * DM];
__device__ __nv_bfloat16 g_Cl[NR * DM];
__device__ __nv_bfloat16 g_Vt[(size_t)BATCH * 4 * 32 * SEQ];  // [bh][v][s]
__device__ int   g_mask_mode;   // 0=uint8, 1=int32, 2=float32

// ---------------------------------------------------------------------------
__device__ __forceinline__ float ex2(float y)
{
    float r;
    asm("ex2.approx.f32 %0, %1;" : "=f"(r) : "f"(y));
    return r;
}

__device__ __forceinline__ uint32_t pack_bf16x2(float lo, float hi)
{
    uint32_t r;
    asm("cvt.rn.bf16x2.f32 %0, %1, %2;" : "=r"(r) : "f"(hi), "f"(lo));
    return r;
}

__device__ __forceinline__ uint32_t bf16_rn_bits(float x)
{
    uint32_t b = __float_as_uint(x);
    return (b + 0x7fffu + ((b >> 16) & 1u)) >> 16;
}

__device__ __forceinline__ void mma16816(float c[4],
                                         uint32_t a0, uint32_t a1, uint32_t a2, uint32_t a3,
                                         uint32_t b0, uint32_t b1)
{
    asm volatile("mma.sync.aligned.m16n8k16.row.col.f32.bf16.bf16.f32 "
                 "{%0,%1,%2,%3}, {%4,%5,%6,%7}, {%8,%9}, {%0,%1,%2,%3};"
                 : "+f"(c[0]), "+f"(c[1]), "+f"(c[2]), "+f"(c[3])
                 : "r"(a0), "r"(a1), "r"(a2), "r"(a3), "r"(b0), "r"(b1));
}

// ldmatrix m8n8.x4 non-trans: lane l supplies address of row (l&7) of tile (l>>3)
__device__ __forceinline__ void ldsm4(uint32_t& r0, uint32_t& r1,
                                      uint32_t& r2, uint32_t& r3, uint32_t addr)
{
    asm volatile("ldmatrix.sync.aligned.m8n8.x4.shared.b16 {%0,%1,%2,%3}, [%4];"
                 : "=r"(r0), "=r"(r1), "=r"(r2), "=r"(r3) : "r"(addr));
}

__device__ __forceinline__ void cp16(const __nv_bfloat16* smem_dst, const void* gsrc)
{
    uint32_t d = (uint32_t)__cvta_generic_to_shared(smem_dst);
    asm volatile("cp.async.cg.shared.global [%0], [%1], 16;" :: "r"(d), "l"(gsrc));
}
__device__ __forceinline__ void cp8(const void* smem_dst, const void* gsrc)
{
    uint32_t d = (uint32_t)__cvta_generic_to_shared(smem_dst);
    asm volatile("cp.async.ca.shared.global [%0], [%1], 8;" :: "r"(d), "l"(gsrc));
}
__device__ __forceinline__ void cp_commit()
{
    asm volatile("cp.async.commit_group;");
}
template <int N>
__device__ __forceinline__ void cp_wait()
{
    asm volatile("cp.async.wait_group %0;" :: "n"(N));
}

// ---------------------------------------------------------------------------
// K0: detect mask dtype.
// ---------------------------------------------------------------------------
__global__ void detect_mask(const unsigned char* __restrict__ m)
{
    __shared__ int s_gt1, s_off;
    if (threadIdx.x == 0) { s_gt1 = 0; s_off = 0; }
    __syncthreads();
    int gt1 = 0, off = 0;
    for (int i = threadIdx.x; i < 4096; i += 256) {
        unsigned char v = m[i];
        if (v > 1) gt1 = 1;
        else if (v == 1 && (i & 3) != 0) off = 1;
    }
    if (gt1) atomicOr(&s_gt1, 1);
    if (off) atomicOr(&s_off, 1);
    __syncthreads();
    if (threadIdx.x == 0)
        g_mask_mode = s_gt1 ? 2 : (s_off ? 0 : 1);
}

// ---------------------------------------------------------------------------
// K0b: pack mask -> bits. One output word (32 flags) per thread.
// ---------------------------------------------------------------------------
__global__ __launch_bounds__(256) void pack_mask(const unsigned char* __restrict__ mask)
{
    const int mode = g_mask_mode;
    size_t wi = (size_t)blockIdx.x * 256 + threadIdx.x;
    uint32_t bits = 0;
    if (mode == 0) {
        const uint4* p = (const uint4*)(mask + wi * 32);
        uint4 a = p[0], b = p[1];
        const uint32_t wa[8] = {a.x, a.y, a.z, a.w, b.x, b.y, b.z, b.w};
#pragma unroll
        for (int q = 0; q < 8; q++) {
            uint32_t v = wa[q];
#pragma unroll
            for (int t = 0; t < 4; t++)
                bits |= (((v >> (t * 8)) & 0xffu) ? 1u : 0u) << (q * 4 + t);
        }
    } else if (mode == 1) {
        const uint4* p = (const uint4*)((const uint32_t*)mask + wi * 32);
#pragma unroll
        for (int q = 0; q < 8; q++) {
            uint4 v = p[q];
            bits |= (v.x ? 1u : 0u) << (q * 4);
            bits |= (v.y ? 1u : 0u) << (q * 4 + 1);
            bits |= (v.z ? 1u : 0u) << (q * 4 + 2);
            bits |= (v.w ? 1u : 0u) << (q * 4 + 3);
        }
    } else {
        const float4* p = (const float4*)((const float*)mask + wi * 32);
#pragma unroll
        for (int q = 0; q < 8; q++) {
            float4 v = p[q];
            bits |= (v.x != 0.f ? 1u : 0u) << (q * 4);
            bits |= (v.y != 0.f ? 1u : 0u) << (q * 4 + 1);
            bits |= (v.z != 0.f ? 1u : 0u) << (q * 4 + 2);
            bits |= (v.w != 0.f ? 1u : 0u) << (q * 4 + 3);
        }
    }
    g_mbits[wi] = bits;
}

// ---------------------------------------------------------------------------
// P0: split inputs fp32 -> bf16 hi/lo.
// ---------------------------------------------------------------------------
__global__ __launch_bounds__(256) void split_inputs(const float* __restrict__ inQ,
                                                    const float* __restrict__ inK,
                                                    const float* __restrict__ inV)
{
    const float* src = (blockIdx.y == 0) ? inQ : (blockIdx.y == 1) ? inK : inV;
    __nv_bfloat16* H = g_Xh + (size_t)blockIdx.y * NR * DM;
    __nv_bfloat16* L = g_Xl + (size_t)blockIdx.y * NR * DM;
    size_t i = ((size_t)blockIdx.x * 256 + threadIdx.x) * 4;
    float4 v = *(const float4*)&src[i];
    uint32_t hx = bf16_rn_bits(v.x), hy = bf16_rn_bits(v.y);
    uint32_t hz = bf16_rn_bits(v.z), hw = bf16_rn_bits(v.w);
    float lx = v.x - __uint_as_float(hx << 16);
    float ly = v.y - __uint_as_float(hy << 16);
    float lz = v.z - __uint_as_float(hz << 16);
    float lw = v.w - __uint_as_float(hw << 16);
    *(uint2*)&H[i] = make_uint2(hx | (hy << 16), hz | (hw << 16));
    *(uint2*)&L[i] = make_uint2(bf16_rn_bits(lx) | (bf16_rn_bits(ly) << 16),
                                bf16_rn_bits(lz) | (bf16_rn_bits(lw) << 16));
}

// ---------------------------------------------------------------------------
// P1: split + transpose weights. grid (8, 5).
// ---------------------------------------------------------------------------
__global__ __launch_bounds__(256) void split_weights(const float* __restrict__ Wfc0,
                                                     const float* __restrict__ WQ,
                                                     const float* __restrict__ WK,
                                                     const float* __restrict__ WV,
                                                     const float* __restrict__ Wfc)
{
    const float* W;
    switch (blockIdx.y) {
        case 0:  W = Wfc0; break;
        case 1:  W = WQ;   break;
        case 2:  W = WK;   break;
        case 3:  W = WV;   break;
        default: W = Wfc;  break;
    }
    __nv_bfloat16* H = g_Wth + blockIdx.y * DM * DM;
    __nv_bfloat16* L = g_Wtl + blockIdx.y * DM * DM;
    int base = (blockIdx.x * 256 + threadIdx.x) * 8;
    int k = base >> 7, n = base & 127;
    float4 v0 = *(const float4*)&W[base];
    float4 v1 = *(const float4*)&W[base + 4];
    const float vs[8] = {v0.x, v0.y, v0.z, v0.w, v1.x, v1.y, v1.z, v1.w};
#pragma unroll
    for (int t = 0; t < 8; t++) {
        float x = vs[t];
        uint32_t hb = bf16_rn_bits(x);
        float lf = x - __uint_as_float(hb << 16);
        ((uint16_t*)H)[(n + t) * DM + k] = (uint16_t)hb;
        ((uint16_t*)L)[(n + t) * DM + k] = (uint16_t)bf16_rn_bits(lf);
    }
}

// ---------------------------------------------------------------------------
// P2: tensor-core projections (unchanged).
// ---------------------------------------------------------------------------
__global__ __launch_bounds__(256, 4) void proj_tc()
{
    extern __shared__ __nv_bfloat16 psm[];
    __nv_bfloat16* sAh  = psm + PA_H;
    __nv_bfloat16* sAl  = psm + PA_L;
    __nv_bfloat16* sWth = psm + PW_H;
    __nv_bfloat16* sWtl = psm + PW_L;

    const int tid  = threadIdx.x;
    const int w    = tid >> 5;
    const int lane = tid & 31;
    const int g    = lane >> 2;
    const int tig  = lane & 3;
    const int gm   = blockIdx.y;
    const int r0   = blockIdx.x * 64;

    const int xsel = (gm <= 1) ? 0 : (gm - 1);
    const __nv_bfloat16* gXh = g_Xh + (size_t)xsel * NR * DM;
    const __nv_bfloat16* gXl = g_Xl + (size_t)xsel * NR * DM;
    const __nv_bfloat16* gWh = g_Wth + gm * DM * DM;
    const __nv_bfloat16* gWl = g_Wtl + gm * DM * DM;

    const int mt = w >> 1;
    const int nh = (w & 1) * 64;
    const int m0 = mt * 16 + g;
    const int m1 = m0 + 8;

    float acc[8][4];
#pragma unroll
    for (int nt = 0; nt < 8; nt++)
#pragma unroll
        for (int i = 0; i < 4; i++) acc[nt][i] = 0.f;

    for (int ks = 0; ks < 2; ks++) {
        if (ks) __syncthreads();
        {
#pragma unroll
            for (int it = 0; it < 2; it++) {
                int id = tid + it * 256;
                int row = id >> 3, seg = (id & 7) * 8;
                size_t src = (size_t)(r0 + row) * DM + ks * 64 + seg;
                cp16(sAh + row * PSTR + seg, gXh + src);
                cp16(sAl + row * PSTR + seg, gXl + src);
            }
#pragma unroll
            for (int it = 0; it < 4; it++) {
                int id = tid + it * 256;
                int n = id >> 3, seg = (id & 7) * 8;
                size_t src = (size_t)n * DM + ks * 64 + seg;
                cp16(sWth + n * PSTR + seg, gWh + src);
                cp16(sWtl + n * PSTR + seg, gWl + src);
            }
        }
        cp_commit();
        cp_wait<0>();
        __syncthreads();

#pragma unroll
        for (int kk = 0; kk < 64; kk += 16) {
            const int dof = kk + tig * 2;
            uint32_t ah0 = *(const uint32_t*)&sAh[m0 * PSTR + dof];
            uint32_t ah1 = *(const uint32_t*)&sAh[m1 * PSTR + dof];
            uint32_t ah2 = *(const uint32_t*)&sAh[m0 * PSTR + dof + 8];
            uint32_t ah3 = *(const uint32_t*)&sAh[m1 * PSTR + dof + 8];
            uint32_t al0 = *(const uint32_t*)&sAl[m0 * PSTR + dof];
            uint32_t al1 = *(const uint32_t*)&sAl[m1 * PSTR + dof];
            uint32_t al2 = *(const uint32_t*)&sAl[m0 * PSTR + dof + 8];
            uint32_t al3 = *(const uint32_t*)&sAl[m1 * PSTR + dof + 8];
#pragma unroll
            for (int nt = 0; nt < 8; nt++) {
                int ncol = nh + nt * 8 + g;
                uint32_t bh0 = *(const uint32_t*)&sWth[ncol * PSTR + dof];
                uint32_t bh1 = *(const uint32_t*)&sWth[ncol * PSTR + dof + 8];
                uint32_t bl0 = *(const uint32_t*)&sWtl[ncol * PSTR + dof];
                uint32_t bl1 = *(const uint32_t*)&sWtl[ncol * PSTR + dof + 8];
                mma16816(acc[nt], ah0, ah1, ah2, ah3, bh0, bh1);
                mma16816(acc[nt], ah0, ah1, ah2, ah3, bl0, bl1);
                mma16816(acc[nt], al0, al1, al2, al3, bh0, bh1);
            }
        }
    }

    const size_t row0 = (size_t)(r0 + m0);
    const size_t row1 = row0 + 8;

    if (gm == 0) {
#pragma unroll
        for (int nt = 0; nt < 8; nt++) {
            int col = nh + nt * 8 + tig * 2;
            *(float2*)&g_R[row0 * DM + col] = make_float2(acc[nt][0], acc[nt][1]);
            *(float2*)&g_R[row1 * DM + col] = make_float2(acc[nt][2], acc[nt][3]);
        }
    } else if (gm == 1 || gm == 2) {
        __nv_bfloat16* H = (gm == 1) ? g_Qh : g_Kh;
        __nv_bfloat16* L = (gm == 1) ? g_Ql : g_Kl;
#pragma unroll
        for (int nt = 0; nt < 8; nt++) {
            int col = nh + nt * 8 + tig * 2;
#pragma unroll
            for (int rr = 0; rr < 2; rr++) {
                float f0 = acc[nt][rr * 2], f1 = acc[nt][rr * 2 + 1];
                uint32_t h0 = bf16_rn_bits(f0), h1 = bf16_rn_bits(f1);
                float l0 = f0 - __uint_as_float(h0 << 16);
                float l1 = f1 - __uint_as_float(h1 << 16);
                size_t off = (rr ? row1 : row0) * DM + col;
                *(uint32_t*)&H[off] = h0 | (h1 << 16);
                *(uint32_t*)&L[off] = bf16_rn_bits(l0) | (bf16_rn_bits(l1) << 16);
            }
        }
    } else {
        uint16_t* sV = (uint16_t*)(psm + PW_H);
        __syncthreads();
#pragma unroll
        for (int nt = 0; nt < 8; nt++) {
            int col = nh + nt * 8 + tig * 2;
            *(uint32_t*)&sV[m0 * VSTR + col] =
                bf16_rn_bits(acc[nt][0]) | (bf16_rn_bits(acc[nt][1]) << 16);
            *(uint32_t*)&sV[m1 * VSTR + col] =
                bf16_rn_bits(acc[nt][2]) | (bf16_rn_bits(acc[nt][3]) << 16);
        }
        __syncthreads();
        const int v   = tid >> 3;
        const int seg = (tid & 7) * 8;
        const int b   = r0 / SEQ;
        const int sblock = r0 % SEQ;
#pragma unroll
        for (int hd = 0; hd < 4; hd++) {
            uint32_t wv[4];
#pragma unroll
            for (int p = 0; p < 4; p++) {
                uint32_t lo = sV[(seg + p * 2) * VSTR + hd * 32 + v];
                uint32_t hi = sV[(seg + p * 2 + 1) * VSTR + hd * 32 + v];
                wv[p] = lo | (hi << 16);
            }
            size_t off = ((size_t)(b * 4 + hd) * 32 + v) * SEQ + sblock + seg;
            *(uint4*)&g_Vt[off] = make_uint4(wv[0], wv[1], wv[2], wv[3]);
        }
    }
}

// ---------------------------------------------------------------------------
// K1.5: rowsum pre-pass, 2-product scores; K frags via ldmatrix.
// ---------------------------------------------------------------------------
__global__ __launch_bounds__(256, 4) void rowsum_pass()
{
    extern __shared__ __nv_bfloat16 smb[];
    uint32_t* mw = (uint32_t*)(smb + 3 * KBUF);   // [3][128][2] words
    __shared__ float srow[128];

    const int tid  = threadIdx.x;
    const int w    = tid >> 5;
    const int lane = tid & 31;
    const int g    = lane >> 2;
    const int tig  = lane & 3;
    const int qb   = w * 16;

    const int bh = blockIdx.y;
    const int b = bh >> 2, h = bh & 3;
    const int q0 = blockIdx.x * TQ;
    const float CE = 1.4426950408889634f * 0.17677669529663689f;
    const size_t bS = (size_t)b * SEQ;

    const int kj   = tid >> 2;
    const int kseg = (tid & 3) * 8;
    const __nv_bfloat16* gK_h = g_Kh + bS * DM + h * 32;
    const uint32_t* gMB = g_mbits + (bS + q0) * SW;

    // ldmatrix lane offsets: row (lane&7), k-tile (lane>>3)*8
    const uint32_t smbA = (uint32_t)__cvta_generic_to_shared(smb);
    const uint32_t lofs = (((lane & 7) * QSTR) + (lane >> 3) * 8) * 2;

    auto issue_chunk = [&](int kc) {
        cp16(smb + (kc % 3) * KBUF + kj * QSTR + kseg,
             gK_h + (size_t)(kc * TK + kj) * DM + kseg);
        if (tid < 128)
            cp8(mw + (kc % 3) * 256 + tid * 2, gMB + (size_t)tid * SW + kc * 2);
    };
    issue_chunk(0);
    cp_commit();
    issue_chunk(1);
    cp_commit();

    uint32_t qh[2][4], ql[2][4];
    {
        const __nv_bfloat16* gQ_h = g_Qh + (bS + q0) * DM + h * 32;
        const __nv_bfloat16* gQ_l = g_Ql + (bS + q0) * DM + h * 32;
#pragma unroll
        for (int kk = 0; kk < 2; kk++) {
            int c0 = kk * 16 + tig * 2;
            size_t r0o = (size_t)(qb + g) * DM + c0;
            size_t r1o = (size_t)(qb + g + 8) * DM + c0;
            qh[kk][0] = *(const uint32_t*)&gQ_h[r0o];
            qh[kk][1] = *(const uint32_t*)&gQ_h[r1o];
            qh[kk][2] = *(const uint32_t*)&gQ_h[r0o + 8];
            qh[kk][3] = *(const uint32_t*)&gQ_h[r1o + 8];
            ql[kk][0] = *(const uint32_t*)&gQ_l[r0o];
            ql[kk][1] = *(const uint32_t*)&gQ_l[r1o];
            ql[kk][2] = *(const uint32_t*)&gQ_l[r0o + 8];
            ql[kk][3] = *(const uint32_t*)&gQ_l[r1o + 8];
        }
    }

    float rs0 = 0.f, rs1 = 0.f;

    for (int kc = 0; kc < NC; kc++) {
        cp_wait<1>();
        __syncthreads();
        if (kc + 2 < NC) issue_chunk(kc + 2);
        cp_commit();

        const uint32_t khA = smbA + ((kc % 3) * KBUF) * 2 + lofs;
        const uint2 mw0 = *(const uint2*)&mw[(kc % 3) * 256 + (qb + g) * 2];
        const uint2 mw1 = *(const uint2*)&mw[(kc % 3) * 256 + (qb + g + 8) * 2];

#pragma unroll
        for (int jj = 0; jj < 4; jj++) {
            const uint32_t w0 = (jj < 2) ? mw0.x : mw0.y;
            const uint32_t w1 = (jj < 2) ? mw1.x : mw1.y;

            // K-hi frags: regs [kk0-b0, kk0-b1, kk1-b0, kk1-b1] per s
            uint32_t k0f[4], k1f[4];
            ldsm4(k0f[0], k0f[1], k0f[2], k0f[3], khA + (jj * 16) * QSTR * 2);
            ldsm4(k1f[0], k1f[1], k1f[2], k1f[3], khA + (jj * 16 + 8) * QSTR * 2);

#pragma unroll
            for (int s = 0; s < 2; s++) {
                const uint32_t* kf = s ? k1f : k0f;
                float c[4]  = {0.f, 0.f, 0.f, 0.f};
                float c2[4] = {0.f, 0.f, 0.f, 0.f};
                mma16816(c, qh[0][0], qh[0][1], qh[0][2], qh[0][3], kf[0], kf[1]);
                mma16816(c, ql[0][0], ql[0][1], ql[0][2], ql[0][3], kf[0], kf[1]);
                mma16816(c2, qh[1][0], qh[1][1], qh[1][2], qh[1][3], kf[2], kf[3]);
                mma16816(c2, ql[1][0], ql[1][1], ql[1][2], ql[1][3], kf[2], kf[3]);
#pragma unroll
                for (int i = 0; i < 4; i++) c[i] += c2[i];
                const int bp = ((jj & 1) * 16 + s * 8 + tig * 2);
                rs0 += (((w0 >> bp) & 1) ? 0.f : ex2(c[0] * CE))
                     + (((w0 >> (bp + 1)) & 1) ? 0.f : ex2(c[1] * CE));
                rs1 += (((w1 >> bp) & 1) ? 0.f : ex2(c[2] * CE))
                     + (((w1 >> (bp + 1)) & 1) ? 0.f : ex2(c[3] * CE));
            }
        }
    }

    rs0 += __shfl_xor_sync(0xffffffff, rs0, 1);
    rs0 += __shfl_xor_sync(0xffffffff, rs0, 2);
    rs1 += __shfl_xor_sync(0xffffffff, rs1, 1);
    rs1 += __shfl_xor_sync(0xffffffff, rs1, 2);
    __syncthreads();
    if (tig == 0) {
        srow[qb + g]     = rs0;
        srow[qb + g + 8] = rs1;
    }
    __syncthreads();
    if (tid < 128)
        g_rinv[(size_t)bh * SEQ + q0 + tid] = 1.0f / srow[tid];
}

// ---------------------------------------------------------------------------
// K2: tensor-core attention; K/V frags via ldmatrix; attn written NORMALIZED.
// ---------------------------------------------------------------------------
__global__ __launch_bounds__(256, 4) void attn_mma(float* __restrict__ attn)
{
    extern __shared__ __nv_bfloat16 smb[];
    uint32_t* mw = (uint32_t*)(smb + SMEM_BF16);   // [3][128][2] words

    const int tid  = threadIdx.x;
    const int w    = tid >> 5;
    const int lane = tid & 31;
    const int g    = lane >> 2;
    const int tig  = lane & 3;
    const int qb   = w * 16;

    const int bh = blockIdx.y;
    const int b = bh >> 2, h = bh & 3;
    const int q0 = blockIdx.x * TQ;
    const float CE = 1.4426950408889634f * 0.17677669529663689f;
    const size_t bS = (size_t)b * SEQ;

    const int kj   = tid >> 2;
    const int kseg = (tid & 3) * 8;
    const int vv   = tid >> 3;
    const int vseg = (tid & 7) * 8;
    const __nv_bfloat16* gK_h = g_Kh + bS * DM + h * 32;
    const __nv_bfloat16* gK_l = g_Kl + bS * DM + h * 32;
    const __nv_bfloat16* gV_t = g_Vt + ((size_t)bh * 32 + vv) * SEQ;
    const uint32_t* gMB = g_mbits + (bS + q0) * SW;

    // ldmatrix lane offsets
    const uint32_t smbA = (uint32_t)__cvta_generic_to_shared(smb);
    const uint32_t klofs = (((lane & 7) * QSTR) + (lane >> 3) * 8) * 2;
    const uint32_t vlofs = ((((lane >> 4) * 8 + (lane & 7)) * ESTR) + ((lane >> 3) & 1) * 8) * 2;

    auto issue_chunk = [&](int kc) {
        __nv_bfloat16* kh = smb + (kc % 3) * BUF_SZ;
        __nv_bfloat16* kl = kh + 64 * QSTR;
        __nv_bfloat16* vh = kl + 64 * QSTR;
        size_t koff = (size_t)(kc * TK + kj) * DM + kseg;
        cp16(kh + kj * QSTR + kseg, gK_h + koff);
        cp16(kl + kj * QSTR + kseg, gK_l + koff);
        cp16(vh + vv * ESTR + vseg, gV_t + kc * TK + vseg);
        if (tid < 128)
            cp8(mw + (kc % 3) * 256 + tid * 2, gMB + (size_t)tid * SW + kc * 2);
    };

    issue_chunk(0);
    cp_commit();
    issue_chunk(1);
    cp_commit();

    uint32_t qh[2][4], ql[2][4];
    {
        const __nv_bfloat16* gQ_h = g_Qh + (bS + q0) * DM + h * 32;
        const __nv_bfloat16* gQ_l = g_Ql + (bS + q0) * DM + h * 32;
#pragma unroll
        for (int kk = 0; kk < 2; kk++) {
            int c0 = kk * 16 + tig * 2;
            size_t r0o = (size_t)(qb + g) * DM + c0;
            size_t r1o = (size_t)(qb + g + 8) * DM + c0;
            qh[kk][0] = *(const uint32_t*)&gQ_h[r0o];
            qh[kk][1] = *(const uint32_t*)&gQ_h[r1o];
            qh[kk][2] = *(const uint32_t*)&gQ_h[r0o + 8];
            qh[kk][3] = *(const uint32_t*)&gQ_h[r1o + 8];
            ql[kk][0] = *(const uint32_t*)&gQ_l[r0o];
            ql[kk][1] = *(const uint32_t*)&gQ_l[r1o];
            ql[kk][2] = *(const uint32_t*)&gQ_l[r0o + 8];
            ql[kk][3] = *(const uint32_t*)&gQ_l[r1o + 8];
        }
    }

    const int qg0 = q0 + qb + g;
    const float rinv0 = g_rinv[(size_t)bh * SEQ + qg0];
    const float rinv1 = g_rinv[(size_t)bh * SEQ + qg0 + 8];

    float cacc[4][4];
#pragma unroll
    for (int n = 0; n < 4; n++)
#pragma unroll
        for (int i = 0; i < 4; i++) cacc[n][i] = 0.f;

    const size_t arow0 = ((size_t)bh * SEQ + qg0) * SEQ;
    const size_t arow1 = arow0 + 8 * SEQ;

    for (int kc = 0; kc < NC; kc++) {
        const int k0 = kc * TK;

        cp_wait<1>();
        __syncthreads();
        if (kc + 2 < NC) issue_chunk(kc + 2);
        cp_commit();

        const uint32_t bufA = smbA + ((kc % 3) * BUF_SZ) * 2;
        const uint32_t khA = bufA + klofs;
        const uint32_t klA = khA + (64 * QSTR) * 2;
        const uint32_t vhA = bufA + (128 * QSTR) * 2 + vlofs;
        const uint2 mw0 = *(const uint2*)&mw[(kc % 3) * 256 + (qb + g) * 2];
        const uint2 mw1 = *(const uint2*)&mw[(kc % 3) * 256 + (qb + g + 8) * 2];

#pragma unroll
        for (int jj = 0; jj < 4; jj++) {
            const uint32_t w0 = (jj < 2) ? mw0.x : mw0.y;
            const uint32_t w1 = (jj < 2) ? mw1.x : mw1.y;

            // K fragments via ldmatrix: [kk0-b0, kk0-b1, kk1-b0, kk1-b1]
            uint32_t kh0[4], kh1[4], kl0[4], kl1[4];
            ldsm4(kh0[0], kh0[1], kh0[2], kh0[3], khA + (jj * 16) * QSTR * 2);
            ldsm4(kh1[0], kh1[1], kh1[2], kh1[3], khA + (jj * 16 + 8) * QSTR * 2);
            ldsm4(kl0[0], kl0[1], kl0[2], kl0[3], klA + (jj * 16) * QSTR * 2);
            ldsm4(kl1[0], kl1[1], kl1[2], kl1[3], klA + (jj * 16 + 8) * QSTR * 2);

            uint32_t eh[2][2];
#pragma unroll
            for (int s = 0; s < 2; s++) {
                const uint32_t* khf = s ? kh1 : kh0;
                const uint32_t* klf = s ? kl1 : kl0;
                float c[4]  = {0.f, 0.f, 0.f, 0.f};
                float c2[4] = {0.f, 0.f, 0.f, 0.f};
                mma16816(c, qh[0][0], qh[0][1], qh[0][2], qh[0][3], khf[0], khf[1]);
                mma16816(c, qh[0][0], qh[0][1], qh[0][2], qh[0][3], klf[0], klf[1]);
                mma16816(c, ql[0][0], ql[0][1], ql[0][2], ql[0][3], khf[0], khf[1]);
                mma16816(c2, qh[1][0], qh[1][1], qh[1][2], qh[1][3], khf[2], khf[3]);
                mma16816(c2, qh[1][0], qh[1][1], qh[1][2], qh[1][3], klf[2], klf[3]);
                mma16816(c2, ql[1][0], ql[1][1], ql[1][2], ql[1][3], khf[2], khf[3]);
#pragma unroll
                for (int i = 0; i < 4; i++) c[i] += c2[i];

                const int jgl = k0 + jj * 16 + s * 8 + tig * 2;
                const int bp = ((jj & 1) * 16 + s * 8 + tig * 2);
                float e00 = ((w0 >> bp) & 1)       ? 0.f : ex2(c[0] * CE) * rinv0;
                float e01 = ((w0 >> (bp + 1)) & 1) ? 0.f : ex2(c[1] * CE) * rinv0;
                float e10 = ((w1 >> bp) & 1)       ? 0.f : ex2(c[2] * CE) * rinv1;
                float e11 = ((w1 >> (bp + 1)) & 1) ? 0.f : ex2(c[3] * CE) * rinv1;
                *(float2*)(attn + arow0 + jgl) = make_float2(e00, e01);
                *(float2*)(attn + arow1 + jgl) = make_float2(e10, e11);
                eh[s][0] = pack_bf16x2(e00, e01);
                eh[s][1] = pack_bf16x2(e10, e11);
            }

            // V fragments via ldmatrix: va = [vb0(nt0), vb1(nt0), vb0(nt1), vb1(nt1)]
            uint32_t va[4], vb[4];
            ldsm4(va[0], va[1], va[2], va[3], vhA + (jj * 16) * 2);
            ldsm4(vb[0], vb[1], vb[2], vb[3], vhA + (16 * ESTR + jj * 16) * 2);
            mma16816(cacc[0], eh[0][0], eh[0][1], eh[1][0], eh[1][1], va[0], va[1]);
            mma16816(cacc[1], eh[0][0], eh[0][1], eh[1][0], eh[1][1], va[2], va[3]);
            mma16816(cacc[2], eh[0][0], eh[0][1], eh[1][0], eh[1][1], vb[0], vb[1]);
            mma16816(cacc[3], eh[0][0], eh[0][1], eh[1][0], eh[1][1], vb[2], vb[3]);
        }
    }

    // ---- ctx write as bf16 hi/lo ----
    {
        size_t row0 = (bS + q0 + qb + g) * (size_t)DM + h * 32;
        size_t row1 = row0 + 8 * DM;
#pragma unroll
        for (int nt = 0; nt < 4; nt++) {
            int v = nt * 8 + tig * 2;
#pragma unroll
            for (int rr = 0; rr < 2; rr++) {
                float f0 = cacc[nt][rr * 2], f1 = cacc[nt][rr * 2 + 1];
                uint32_t h0 = bf16_rn_bits(f0), h1 = bf16_rn_bits(f1);
                float l0 = f0 - __uint_as_float(h0 << 16);
                float l1 = f1 - __uint_as_float(h1 << 16);
                size_t off = (rr ? row1 : row0) + v;
                *(uint32_t*)&g_Ch[off] = h0 | (h1 << 16);
                *(uint32_t*)&g_Cl[off] = bf16_rn_bits(l0) | (bf16_rn_bits(l1) << 16);
            }
        }
    }
}

// ---------------------------------------------------------------------------
// K4: out = LayerNorm(ctx @ W_fc + g_R), tensor-core.
// ---------------------------------------------------------------------------
__global__ __launch_bounds__(256) void out_ln_tc(const float* __restrict__ gamma,
                                                 const float* __restrict__ beta,
                                                 float* __restrict__ out)
{
    extern __shared__ __nv_bfloat16 psm[];
    __nv_bfloat16* sAh  = psm + PA_H;
    __nv_bfloat16* sAl  = psm + PA_L;
    __nv_bfloat16* sWth = psm + PW_H;
    __nv_bfloat16* sWtl = psm + PW_L;

    const int tid  = threadIdx.x;
    const int w    = tid >> 5;
    const int lane = tid & 31;
    const int g    = lane >> 2;
    const int tig  = lane & 3;
    const int r0   = blockIdx.x * 64;

    const __nv_bfloat16* gWh = g_Wth + 4 * DM * DM;
    const __nv_bfloat16* gWl = g_Wtl + 4 * DM * DM;

    const int mt = w >> 1;
    const int nh = (w & 1) * 64;
    const int m0 = mt * 16 + g;
    const int m1 = m0 + 8;

    float acc[8][4];
#pragma unroll
    for (int nt = 0; nt < 8; nt++)
#pragma unroll
        for (int i = 0; i < 4; i++) acc[nt][i] = 0.f;

    for (int ks = 0; ks < 2; ks++) {
        if (ks) __syncthreads();
        {
#pragma unroll
            for (int it = 0; it < 2; it++) {
                int id = tid + it * 256;
                int row = id >> 3, seg = (id & 7) * 8;
                size_t src = (size_t)(r0 + row) * DM + ks * 64 + seg;
                cp16(sAh + row * PSTR + seg, g_Ch + src);
                cp16(sAl + row * PSTR + seg, g_Cl + src);
            }
#pragma unroll
            for (int it = 0; it < 4; it++) {
                int id = tid + it * 256;
                int n = id >> 3, seg = (id & 7) * 8;
                size_t src = (size_t)n * DM + ks * 64 + seg;
                cp16(sWth + n * PSTR + seg, gWh + src);
                cp16(sWtl + n * PSTR + seg, gWl + src);
            }
        }
        cp_commit();
        cp_wait<0>();
        __syncthreads();

#pragma unroll
        for (int kk = 0; kk < 64; kk += 16) {
            const int dof = kk + tig * 2;
            uint32_t ah0 = *(const uint32_t*)&sAh[m0 * PSTR + dof];
            uint32_t ah1 = *(const uint32_t*)&sAh[m1 * PSTR + dof];
            uint32_t ah2 = *(const uint32_t*)&sAh[m0 * PSTR + dof + 8];
            uint32_t ah3 = *(const uint32_t*)&sAh[m1 * PSTR + dof + 8];
            uint32_t al0 = *(const uint32_t*)&sAl[m0 * PSTR + dof];
            uint32_t al1 = *(const uint32_t*)&sAl[m1 * PSTR + dof];
            uint32_t al2 = *(const uint32_t*)&sAl[m0 * PSTR + dof + 8];
            uint32_t al3 = *(const uint32_t*)&sAl[m1 * PSTR + dof + 8];
#pragma unroll
            for (int nt = 0; nt < 8; nt++) {
                int ncol = nh + nt * 8 + g;
                uint32_t bh0 = *(const uint32_t*)&sWth[ncol * PSTR + dof];
                uint32_t bh1 = *(const uint32_t*)&sWth[ncol * PSTR + dof + 8];
                uint32_t bl0 = *(const uint32_t*)&sWtl[ncol * PSTR + dof];
                uint32_t bl1 = *(const uint32_t*)&sWtl[ncol * PSTR + dof + 8];
                mma16816(acc[nt], ah0, ah1, ah2, ah3, bh0, bh1);
                mma16816(acc[nt], ah0, ah1, ah2, ah3, bl0, bl1);
                mma16816(acc[nt], al0, al1, al2, al3, bh0, bh1);
            }
        }
    }

    const size_t row0 = (size_t)(r0 + m0);
    const size_t row1 = row0 + 8;
    float ps0 = 0.f, pq0 = 0.f, ps1 = 0.f, pq1 = 0.f;
#pragma unroll
    for (int nt = 0; nt < 8; nt++) {
        int col = nh + nt * 8 + tig * 2;
        float2 rv0 = *(const float2*)&g_R[row0 * DM + col];
        float2 rv1 = *(const float2*)&g_R[row1 * DM + col];
        acc[nt][0] += rv0.x; acc[nt][1] += rv0.y;
        acc[nt][2] += rv1.x; acc[nt][3] += rv1.y;
        ps0 += acc[nt][0] + acc[nt][1];
        pq0 += acc[nt][0] * acc[nt][0] + acc[nt][1] * acc[nt][1];
        ps1 += acc[nt][2] + acc[nt][3];
        pq1 += acc[nt][2] * acc[nt][2] + acc[nt][3] * acc[nt][3];
    }

    float* red1 = (float*)psm;
    float* red2 = red1 + 64 * 8;
    float* smu  = red2 + 64 * 8;
    float* srs  = smu + 64;
    __syncthreads();
    const int slot = (w & 1) * 4 + tig;
    red1[m0 * 8 + slot] = ps0;
    red2[m0 * 8 + slot] = pq0;
    red1[m1 * 8 + slot] = ps1;
    red2[m1 * 8 + slot] = pq1;
    __syncthreads();
    if (tid < 64) {
        float s = 0.f, q = 0.f;
#pragma unroll
        for (int j = 0; j < 8; j++) { s += red1[tid * 8 + j]; q += red2[tid * 8 + j]; }
        float mu = s * (1.0f / 128.0f);
        float var = q * (1.0f / 128.0f) - mu * mu;
        smu[tid] = mu;
        srs[tid] = rsqrtf(var + 1e-5f);
    }
    __syncthreads();

    const float mu0 = smu[m0], rs0 = srs[m0];
    const float mu1 = smu[m1], rs1 = srs[m1];
#pragma unroll
    for (int nt = 0; nt < 8; nt++) {
        int col = nh + nt * 8 + tig * 2;
        float2 gm = *(const float2*)&gamma[col];
        float2 bt = *(const float2*)&beta[col];
        float2 o0 = make_float2((acc[nt][0] - mu0) * rs0 * gm.x + bt.x,
                                (acc[nt][1] - mu0) * rs0 * gm.y + bt.y);
        float2 o1 = make_float2((acc[nt][2] - mu1) * rs1 * gm.x + bt.x,
                                (acc[nt][3] - mu1) * rs1 * gm.y + bt.y);
        *(float2*)&out[row0 * DM + col] = o0;
        *(float2*)&out[row1 * DM + col] = o1;
    }
}

// ---------------------------------------------------------------------------
extern "C" void kernel_launch(void* const* d_in, const int* in_sizes, int n_in,
                              void* d_out, int out_size)
{
    const float* inQ  = (const float*)d_in[0];
    const float* inK  = (const float*)d_in[1];
    const float* inV  = (const float*)d_in[2];
    const unsigned char* mask = (const unsigned char*)d_in[3];
    const float* Wfc0 = (const float*)d_in[4];
    const float* WQ   = (const float*)d_in[5];
    const float* WK   = (const float*)d_in[6];
    const float* WV   = (const float*)d_in[7];
    const float* Wfc  = (const float*)d_in[8];
    const float* gam  = (const float*)d_in[9];
    const float* bet  = (const float*)d_in[10];
    float* out  = (float*)d_out;
    float* attn = out + OUT_ELEMS;

    detect_mask<<<1, 256>>>(mask);                                  // 1
    pack_mask<<<(unsigned)((size_t)BATCH * SEQ * SW / 256), 256>>>(mask);  // 2
    split_inputs<<<dim3(NR * DM / 1024, 3), 256>>>(inQ, inK, inV);  // 3
    split_weights<<<dim3(8, 5), 256>>>(Wfc0, WQ, WK, WV, Wfc);      // 4

    cudaFuncSetAttribute(proj_tc, cudaFuncAttributeMaxDynamicSharedMemorySize,
                         (int)P_SMEM_BYTES);
    proj_tc<<<dim3(NR / 64, 4), 256, P_SMEM_BYTES>>>();             // 5

    dim3 agrid(SEQ / TQ, BATCH * 4);
    cudaFuncSetAttribute(rowsum_pass, cudaFuncAttributeMaxDynamicSharedMemorySize,
                         (int)RS_SMEM_BYTES);
    rowsum_pass<<<agrid, 256, RS_SMEM_BYTES>>>();                   // 6 (ncu)

    cudaFuncSetAttribute(attn_mma, cudaFuncAttributeMaxDynamicSharedMemorySize,
                         (int)SMEM_BYTES);
    attn_mma<<<agrid, 256, SMEM_BYTES>>>(attn);                     // 7

    cudaFuncSetAttribute(out_ln_tc, cudaFuncAttributeMaxDynamicSharedMemorySize,
                         (int)P_SMEM_BYTES);
    out_ln_tc<<<NR / 64, 256, P_SMEM_BYTES>>>(gam, bet, out);       // 8
}

// round 17
// speedup vs baseline: 1.1425x; 1.1425x over previous
#include <cuda_runtime.h>
#include <cuda_bf16.h>
#include <stdint.h>

// ---------------------------------------------------------------------------
// MultiHeadAttention: out = LN(ctx@W_fc + X@W_fc0), attn materialized.
// B=8, S=2048, D=128, H=4, dk=dv=32.
// Output layout: [out (8*2048*128)] then [attn (8*4*2048*2048)].
// R17: TQ=256 in rowsum/attn (each warp: 32 q-rows, K/V fragments loaded once
// per chunk and reused across two q-sets -> L1 bytes/q-row -39%). ldmatrix
// reverted (R16 proved instruction count is not the binding pipe).
// ---------------------------------------------------------------------------

namespace {
constexpr int BATCH = 8;
constexpr int SEQ   = 2048;
constexpr int DM    = 128;
constexpr int NR    = BATCH * SEQ;                 // 16384 rows
constexpr size_t OUT_ELEMS = (size_t)NR * DM;      // 2,097,152
constexpr int TQ = 256;                            // q-tile per block (2 q-sets)
constexpr int TK = 64;                             // k-chunk
constexpr int NC = SEQ / TK;                       // 32 chunks
constexpr int SW = SEQ / 32;                       // 64 mask words per row

// attn_mma smem (bf16 units) + mask word region
constexpr int QSTR = 40;
constexpr int ESTR = 72;
constexpr int BUF_SZ  = 64 * QSTR * 2 + 32 * ESTR;     // 7424 bf16
constexpr int SMEM_BF16 = 3 * BUF_SZ;                  // 22272
constexpr size_t MW_BYTES = 3 * 256 * 2 * 4;           // 6144 B (3 bufs x 256 rows x 2 words)
constexpr size_t SMEM_BYTES = (size_t)SMEM_BF16 * 2 + MW_BYTES;  // 50,688 B

// rowsum_pass smem
constexpr int KBUF = 64 * QSTR;                        // 2560 bf16
constexpr size_t RS_SMEM_BYTES = (size_t)(3 * KBUF) * 2 + MW_BYTES;  // 21,504 B

// proj_tc / out_ln_tc smem
constexpr int PSTR = 72;
constexpr int PA_H = 0;
constexpr int PA_L = PA_H + 64 * PSTR;
constexpr int PW_H = PA_L + 64 * PSTR;
constexpr int PW_L = PW_H + 128 * PSTR;
constexpr int P_BF16 = PW_L + 128 * PSTR;
constexpr size_t P_SMEM_BYTES = (size_t)P_BF16 * 2;    // 55,296 B
constexpr int VSTR = 136;
}

// Scratch (device globals: allocation-free rule)
__device__ float g_R  [NR * DM];
__device__ float g_rinv[BATCH * 4 * SEQ];
__device__ uint32_t g_mbits[(size_t)BATCH * SEQ * SW];   // 4 MB bit mask
__device__ __nv_bfloat16 g_Xh[3 * NR * DM];
__device__ __nv_bfloat16 g_Xl[3 * NR * DM];
__device__ __nv_bfloat16 g_Wth[5 * DM * DM];
__device__ __nv_bfloat16 g_Wtl[5 * DM * DM];
__device__ __nv_bfloat16 g_Qh[NR * DM];
__device__ __nv_bfloat16 g_Ql[NR * DM];
__device__ __nv_bfloat16 g_Kh[NR * DM];
__device__ __nv_bfloat16 g_Kl[NR * DM];
__device__ __nv_bfloat16 g_Ch[NR * DM];
__device__ __nv_bfloat16 g_Cl[NR * DM];
__device__ __nv_bfloat16 g_Vt[(size_t)BATCH * 4 * 32 * SEQ];  // [bh][v][s]
__device__ int   g_mask_mode;   // 0=uint8, 1=int32, 2=float32

// ---------------------------------------------------------------------------
__device__ __forceinline__ float ex2(float y)
{
    float r;
    asm("ex2.approx.f32 %0, %1;" : "=f"(r) : "f"(y));
    return r;
}

__device__ __forceinline__ uint32_t pack_bf16x2(float lo, float hi)
{
    uint32_t r;
    asm("cvt.rn.bf16x2.f32 %0, %1, %2;" : "=r"(r) : "f"(hi), "f"(lo));
    return r;
}

__device__ __forceinline__ uint32_t bf16_rn_bits(float x)
{
    uint32_t b = __float_as_uint(x);
    return (b + 0x7fffu + ((b >> 16) & 1u)) >> 16;
}

__device__ __forceinline__ void mma16816(float c[4],
                                         uint32_t a0, uint32_t a1, uint32_t a2, uint32_t a3,
                                         uint32_t b0, uint32_t b1)
{
    asm volatile("mma.sync.aligned.m16n8k16.row.col.f32.bf16.bf16.f32 "
                 "{%0,%1,%2,%3}, {%4,%5,%6,%7}, {%8,%9}, {%0,%1,%2,%3};"
                 : "+f"(c[0]), "+f"(c[1]), "+f"(c[2]), "+f"(c[3])
                 : "r"(a0), "r"(a1), "r"(a2), "r"(a3), "r"(b0), "r"(b1));
}

__device__ __forceinline__ void cp16(const __nv_bfloat16* smem_dst, const void* gsrc)
{
    uint32_t d = (uint32_t)__cvta_generic_to_shared(smem_dst);
    asm volatile("cp.async.cg.shared.global [%0], [%1], 16;" :: "r"(d), "l"(gsrc));
}
__device__ __forceinline__ void cp8(const void* smem_dst, const void* gsrc)
{
    uint32_t d = (uint32_t)__cvta_generic_to_shared(smem_dst);
    asm volatile("cp.async.ca.shared.global [%0], [%1], 8;" :: "r"(d), "l"(gsrc));
}
__device__ __forceinline__ void cp_commit()
{
    asm volatile("cp.async.commit_group;");
}
template <int N>
__device__ __forceinline__ void cp_wait()
{
    asm volatile("cp.async.wait_group %0;" :: "n"(N));
}

// ---------------------------------------------------------------------------
// K0: detect mask dtype.
// ---------------------------------------------------------------------------
__global__ void detect_mask(const unsigned char* __restrict__ m)
{
    __shared__ int s_gt1, s_off;
    if (threadIdx.x == 0) { s_gt1 = 0; s_off = 0; }
    __syncthreads();
    int gt1 = 0, off = 0;
    for (int i = threadIdx.x; i < 4096; i += 256) {
        unsigned char v = m[i];
        if (v > 1) gt1 = 1;
        else if (v == 1 && (i & 3) != 0) off = 1;
    }
    if (gt1) atomicOr(&s_gt1, 1);
    if (off) atomicOr(&s_off, 1);
    __syncthreads();
    if (threadIdx.x == 0)
        g_mask_mode = s_gt1 ? 2 : (s_off ? 0 : 1);
}

// ---------------------------------------------------------------------------
// K0b: pack mask -> bits. One output word (32 flags) per thread.
// ---------------------------------------------------------------------------
__global__ __launch_bounds__(256) void pack_mask(const unsigned char* __restrict__ mask)
{
    const int mode = g_mask_mode;
    size_t wi = (size_t)blockIdx.x * 256 + threadIdx.x;
    uint32_t bits = 0;
    if (mode == 0) {
        const uint4* p = (const uint4*)(mask + wi * 32);
        uint4 a = p[0], b = p[1];
        const uint32_t wa[8] = {a.x, a.y, a.z, a.w, b.x, b.y, b.z, b.w};
#pragma unroll
        for (int q = 0; q < 8; q++) {
            uint32_t v = wa[q];
#pragma unroll
            for (int t = 0; t < 4; t++)
                bits |= (((v >> (t * 8)) & 0xffu) ? 1u : 0u) << (q * 4 + t);
        }
    } else if (mode == 1) {
        const uint4* p = (const uint4*)((const uint32_t*)mask + wi * 32);
#pragma unroll
        for (int q = 0; q < 8; q++) {
            uint4 v = p[q];
            bits |= (v.x ? 1u : 0u) << (q * 4);
            bits |= (v.y ? 1u : 0u) << (q * 4 + 1);
            bits |= (v.z ? 1u : 0u) << (q * 4 + 2);
            bits |= (v.w ? 1u : 0u) << (q * 4 + 3);
        }
    } else {
        const float4* p = (const float4*)((const float*)mask + wi * 32);
#pragma unroll
        for (int q = 0; q < 8; q++) {
            float4 v = p[q];
            bits |= (v.x != 0.f ? 1u : 0u) << (q * 4);
            bits |= (v.y != 0.f ? 1u : 0u) << (q * 4 + 1);
            bits |= (v.z != 0.f ? 1u : 0u) << (q * 4 + 2);
            bits |= (v.w != 0.f ? 1u : 0u) << (q * 4 + 3);
        }
    }
    g_mbits[wi] = bits;
}

// ---------------------------------------------------------------------------
// P0: split inputs fp32 -> bf16 hi/lo.
// ---------------------------------------------------------------------------
__global__ __launch_bounds__(256) void split_inputs(const float* __restrict__ inQ,
                                                    const float* __restrict__ inK,
                                                    const float* __restrict__ inV)
{
    const float* src = (blockIdx.y == 0) ? inQ : (blockIdx.y == 1) ? inK : inV;
    __nv_bfloat16* H = g_Xh + (size_t)blockIdx.y * NR * DM;
    __nv_bfloat16* L = g_Xl + (size_t)blockIdx.y * NR * DM;
    size_t i = ((size_t)blockIdx.x * 256 + threadIdx.x) * 4;
    float4 v = *(const float4*)&src[i];
    uint32_t hx = bf16_rn_bits(v.x), hy = bf16_rn_bits(v.y);
    uint32_t hz = bf16_rn_bits(v.z), hw = bf16_rn_bits(v.w);
    float lx = v.x - __uint_as_float(hx << 16);
    float ly = v.y - __uint_as_float(hy << 16);
    float lz = v.z - __uint_as_float(hz << 16);
    float lw = v.w - __uint_as_float(hw << 16);
    *(uint2*)&H[i] = make_uint2(hx | (hy << 16), hz | (hw << 16));
    *(uint2*)&L[i] = make_uint2(bf16_rn_bits(lx) | (bf16_rn_bits(ly) << 16),
                                bf16_rn_bits(lz) | (bf16_rn_bits(lw) << 16));
}

// ---------------------------------------------------------------------------
// P1: split + transpose weights. grid (8, 5).
// ---------------------------------------------------------------------------
__global__ __launch_bounds__(256) void split_weights(const float* __restrict__ Wfc0,
                                                     const float* __restrict__ WQ,
                                                     const float* __restrict__ WK,
                                                     const float* __restrict__ WV,
                                                     const float* __restrict__ Wfc)
{
    const float* W;
    switch (blockIdx.y) {
        case 0:  W = Wfc0; break;
        case 1:  W = WQ;   break;
        case 2:  W = WK;   break;
        case 3:  W = WV;   break;
        default: W = Wfc;  break;
    }
    __nv_bfloat16* H = g_Wth + blockIdx.y * DM * DM;
    __nv_bfloat16* L = g_Wtl + blockIdx.y * DM * DM;
    int base = (blockIdx.x * 256 + threadIdx.x) * 8;
    int k = base >> 7, n = base & 127;
    float4 v0 = *(const float4*)&W[base];
    float4 v1 = *(const float4*)&W[base + 4];
    const float vs[8] = {v0.x, v0.y, v0.z, v0.w, v1.x, v1.y, v1.z, v1.w};
#pragma unroll
    for (int t = 0; t < 8; t++) {
        float x = vs[t];
        uint32_t hb = bf16_rn_bits(x);
        float lf = x - __uint_as_float(hb << 16);
        ((uint16_t*)H)[(n + t) * DM + k] = (uint16_t)hb;
        ((uint16_t*)L)[(n + t) * DM + k] = (uint16_t)bf16_rn_bits(lf);
    }
}

// ---------------------------------------------------------------------------
// P2: tensor-core projections (unchanged).
// ---------------------------------------------------------------------------
__global__ __launch_bounds__(256, 4) void proj_tc()
{
    extern __shared__ __nv_bfloat16 psm[];
    __nv_bfloat16* sAh  = psm + PA_H;
    __nv_bfloat16* sAl  = psm + PA_L;
    __nv_bfloat16* sWth = psm + PW_H;
    __nv_bfloat16* sWtl = psm + PW_L;

    const int tid  = threadIdx.x;
    const int w    = tid >> 5;
    const int lane = tid & 31;
    const int g    = lane >> 2;
    const int tig  = lane & 3;
    const int gm   = blockIdx.y;
    const int r0   = blockIdx.x * 64;

    const int xsel = (gm <= 1) ? 0 : (gm - 1);
    const __nv_bfloat16* gXh = g_Xh + (size_t)xsel * NR * DM;
    const __nv_bfloat16* gXl = g_Xl + (size_t)xsel * NR * DM;
    const __nv_bfloat16* gWh = g_Wth + gm * DM * DM;
    const __nv_bfloat16* gWl = g_Wtl + gm * DM * DM;

    const int mt = w >> 1;
    const int nh = (w & 1) * 64;
    const int m0 = mt * 16 + g;
    const int m1 = m0 + 8;

    float acc[8][4];
#pragma unroll
    for (int nt = 0; nt < 8; nt++)
#pragma unroll
        for (int i = 0; i < 4; i++) acc[nt][i] = 0.f;

    for (int ks = 0; ks < 2; ks++) {
        if (ks) __syncthreads();
        {
#pragma unroll
            for (int it = 0; it < 2; it++) {
                int id = tid + it * 256;
                int row = id >> 3, seg = (id & 7) * 8;
                size_t src = (size_t)(r0 + row) * DM + ks * 64 + seg;
                cp16(sAh + row * PSTR + seg, gXh + src);
                cp16(sAl + row * PSTR + seg, gXl + src);
            }
#pragma unroll
            for (int it = 0; it < 4; it++) {
                int id = tid + it * 256;
                int n = id >> 3, seg = (id & 7) * 8;
                size_t src = (size_t)n * DM + ks * 64 + seg;
                cp16(sWth + n * PSTR + seg, gWh + src);
                cp16(sWtl + n * PSTR + seg, gWl + src);
            }
        }
        cp_commit();
        cp_wait<0>();
        __syncthreads();

#pragma unroll
        for (int kk = 0; kk < 64; kk += 16) {
            const int dof = kk + tig * 2;
            uint32_t ah0 = *(const uint32_t*)&sAh[m0 * PSTR + dof];
            uint32_t ah1 = *(const uint32_t*)&sAh[m1 * PSTR + dof];
            uint32_t ah2 = *(const uint32_t*)&sAh[m0 * PSTR + dof + 8];
            uint32_t ah3 = *(const uint32_t*)&sAh[m1 * PSTR + dof + 8];
            uint32_t al0 = *(const uint32_t*)&sAl[m0 * PSTR + dof];
            uint32_t al1 = *(const uint32_t*)&sAl[m1 * PSTR + dof];
            uint32_t al2 = *(const uint32_t*)&sAl[m0 * PSTR + dof + 8];
            uint32_t al3 = *(const uint32_t*)&sAl[m1 * PSTR + dof + 8];
#pragma unroll
            for (int nt = 0; nt < 8; nt++) {
                int ncol = nh + nt * 8 + g;
                uint32_t bh0 = *(const uint32_t*)&sWth[ncol * PSTR + dof];
                uint32_t bh1 = *(const uint32_t*)&sWth[ncol * PSTR + dof + 8];
                uint32_t bl0 = *(const uint32_t*)&sWtl[ncol * PSTR + dof];
                uint32_t bl1 = *(const uint32_t*)&sWtl[ncol * PSTR + dof + 8];
                mma16816(acc[nt], ah0, ah1, ah2, ah3, bh0, bh1);
                mma16816(acc[nt], ah0, ah1, ah2, ah3, bl0, bl1);
                mma16816(acc[nt], al0, al1, al2, al3, bh0, bh1);
            }
        }
    }

    const size_t row0 = (size_t)(r0 + m0);
    const size_t row1 = row0 + 8;

    if (gm == 0) {
#pragma unroll
        for (int nt = 0; nt < 8; nt++) {
            int col = nh + nt * 8 + tig * 2;
            *(float2*)&g_R[row0 * DM + col] = make_float2(acc[nt][0], acc[nt][1]);
            *(float2*)&g_R[row1 * DM + col] = make_float2(acc[nt][2], acc[nt][3]);
        }
    } else if (gm == 1 || gm == 2) {
        __nv_bfloat16* H = (gm == 1) ? g_Qh : g_Kh;
        __nv_bfloat16* L = (gm == 1) ? g_Ql : g_Kl;
#pragma unroll
        for (int nt = 0; nt < 8; nt++) {
            int col = nh + nt * 8 + tig * 2;
#pragma unroll
            for (int rr = 0; rr < 2; rr++) {
                float f0 = acc[nt][rr * 2], f1 = acc[nt][rr * 2 + 1];
                uint32_t h0 = bf16_rn_bits(f0), h1 = bf16_rn_bits(f1);
                float l0 = f0 - __uint_as_float(h0 << 16);
                float l1 = f1 - __uint_as_float(h1 << 16);
                size_t off = (rr ? row1 : row0) * DM + col;
                *(uint32_t*)&H[off] = h0 | (h1 << 16);
                *(uint32_t*)&L[off] = bf16_rn_bits(l0) | (bf16_rn_bits(l1) << 16);
            }
        }
    } else {
        uint16_t* sV = (uint16_t*)(psm + PW_H);
        __syncthreads();
#pragma unroll
        for (int nt = 0; nt < 8; nt++) {
            int col = nh + nt * 8 + tig * 2;
            *(uint32_t*)&sV[m0 * VSTR + col] =
                bf16_rn_bits(acc[nt][0]) | (bf16_rn_bits(acc[nt][1]) << 16);
            *(uint32_t*)&sV[m1 * VSTR + col] =
                bf16_rn_bits(acc[nt][2]) | (bf16_rn_bits(acc[nt][3]) << 16);
        }
        __syncthreads();
        const int v   = tid >> 3;
        const int seg = (tid & 7) * 8;
        const int b   = r0 / SEQ;
        const int sblock = r0 % SEQ;
#pragma unroll
        for (int hd = 0; hd < 4; hd++) {
            uint32_t wv[4];
#pragma unroll
            for (int p = 0; p < 4; p++) {
                uint32_t lo = sV[(seg + p * 2) * VSTR + hd * 32 + v];
                uint32_t hi = sV[(seg + p * 2 + 1) * VSTR + hd * 32 + v];
                wv[p] = lo | (hi << 16);
            }
            size_t off = ((size_t)(b * 4 + hd) * 32 + v) * SEQ + sblock + seg;
            *(uint4*)&g_Vt[off] = make_uint4(wv[0], wv[1], wv[2], wv[3]);
        }
    }
}

// ---------------------------------------------------------------------------
// K1.5: rowsum pre-pass, 2-product scores, TQ=256 (two q-sets share K frags).
// ---------------------------------------------------------------------------
__global__ __launch_bounds__(256, 3) void rowsum_pass()
{
    extern __shared__ __nv_bfloat16 smb[];
    uint32_t* mw = (uint32_t*)(smb + 3 * KBUF);   // [3][256][2] words
    __shared__ float srow[256];

    const int tid  = threadIdx.x;
    const int w    = tid >> 5;
    const int lane = tid & 31;
    const int g    = lane >> 2;
    const int tig  = lane & 3;
    const int qb   = w * 32;

    const int bh = blockIdx.y;
    const int b = bh >> 2, h = bh & 3;
    const int q0 = blockIdx.x * TQ;
    const float CE = 1.4426950408889634f * 0.17677669529663689f;
    const size_t bS = (size_t)b * SEQ;

    const int kj   = tid >> 2;
    const int kseg = (tid & 3) * 8;
    const __nv_bfloat16* gK_h = g_Kh + bS * DM + h * 32;
    const uint32_t* gMB = g_mbits + (bS + q0) * SW;

    auto issue_chunk = [&](int kc) {
        cp16(smb + (kc % 3) * KBUF + kj * QSTR + kseg,
             gK_h + (size_t)(kc * TK + kj) * DM + kseg);
        cp8(mw + (kc % 3) * 512 + tid * 2, gMB + (size_t)tid * SW + kc * 2);
    };
    issue_chunk(0);
    cp_commit();
    issue_chunk(1);
    cp_commit();

    // Q fragments for 2 q-sets
    uint32_t qh[2][2][4], ql[2][2][4];
    {
        const __nv_bfloat16* gQ_h = g_Qh + (bS + q0) * DM + h * 32;
        const __nv_bfloat16* gQ_l = g_Ql + (bS + q0) * DM + h * 32;
#pragma unroll
        for (int qs = 0; qs < 2; qs++)
#pragma unroll
            for (int kk = 0; kk < 2; kk++) {
                int c0 = kk * 16 + tig * 2;
                size_t r0o = (size_t)(qb + qs * 16 + g) * DM + c0;
                size_t r1o = r0o + 8 * DM;
                qh[qs][kk][0] = *(const uint32_t*)&gQ_h[r0o];
                qh[qs][kk][1] = *(const uint32_t*)&gQ_h[r1o];
                qh[qs][kk][2] = *(const uint32_t*)&gQ_h[r0o + 8];
                qh[qs][kk][3] = *(const uint32_t*)&gQ_h[r1o + 8];
                ql[qs][kk][0] = *(const uint32_t*)&gQ_l[r0o];
                ql[qs][kk][1] = *(const uint32_t*)&gQ_l[r1o];
                ql[qs][kk][2] = *(const uint32_t*)&gQ_l[r0o + 8];
                ql[qs][kk][3] = *(const uint32_t*)&gQ_l[r1o + 8];
            }
    }

    float rs[4] = {0.f, 0.f, 0.f, 0.f};   // rows qb+g, +8, +16, +24

    for (int kc = 0; kc < NC; kc++) {
        cp_wait<1>();
        __syncthreads();
        if (kc + 2 < NC) issue_chunk(kc + 2);
        cp_commit();

        const __nv_bfloat16* kh = smb + (kc % 3) * KBUF;
        uint2 mwq[4];
#pragma unroll
        for (int r = 0; r < 4; r++)
            mwq[r] = *(const uint2*)&mw[(kc % 3) * 512 + (qb + r * 8 + g) * 2];

#pragma unroll
        for (int jj = 0; jj < 4; jj++) {
#pragma unroll
            for (int s = 0; s < 2; s++) {
                const int j0 = jj * 16 + s * 8;
                const int dof0 = tig * 2;
                const int dof1 = 16 + tig * 2;
                uint32_t b00 = *(const uint32_t*)&kh[(j0 + g) * QSTR + dof0];
                uint32_t b01 = *(const uint32_t*)&kh[(j0 + g) * QSTR + dof0 + 8];
                uint32_t b10 = *(const uint32_t*)&kh[(j0 + g) * QSTR + dof1];
                uint32_t b11 = *(const uint32_t*)&kh[(j0 + g) * QSTR + dof1 + 8];
                const int bp = ((jj & 1) * 16 + s * 8 + tig * 2);
#pragma unroll
                for (int qs = 0; qs < 2; qs++) {
                    float c[4]  = {0.f, 0.f, 0.f, 0.f};
                    float c2[4] = {0.f, 0.f, 0.f, 0.f};
                    mma16816(c, qh[qs][0][0], qh[qs][0][1], qh[qs][0][2], qh[qs][0][3], b00, b01);
                    mma16816(c, ql[qs][0][0], ql[qs][0][1], ql[qs][0][2], ql[qs][0][3], b00, b01);
                    mma16816(c2, qh[qs][1][0], qh[qs][1][1], qh[qs][1][2], qh[qs][1][3], b10, b11);
                    mma16816(c2, ql[qs][1][0], ql[qs][1][1], ql[qs][1][2], ql[qs][1][3], b10, b11);
#pragma unroll
                    for (int i = 0; i < 4; i++) c[i] += c2[i];
                    const uint32_t w0 = (jj < 2) ? mwq[qs * 2].x : mwq[qs * 2].y;
                    const uint32_t w1 = (jj < 2) ? mwq[qs * 2 + 1].x : mwq[qs * 2 + 1].y;
                    rs[qs * 2]     += (((w0 >> bp) & 1) ? 0.f : ex2(c[0] * CE))
                                    + (((w0 >> (bp + 1)) & 1) ? 0.f : ex2(c[1] * CE));
                    rs[qs * 2 + 1] += (((w1 >> bp) & 1) ? 0.f : ex2(c[2] * CE))
                                    + (((w1 >> (bp + 1)) & 1) ? 0.f : ex2(c[3] * CE));
                }
            }
        }
    }

#pragma unroll
    for (int r = 0; r < 4; r++) {
        rs[r] += __shfl_xor_sync(0xffffffff, rs[r], 1);
        rs[r] += __shfl_xor_sync(0xffffffff, rs[r], 2);
    }
    __syncthreads();
    if (tig == 0) {
#pragma unroll
        for (int r = 0; r < 4; r++) srow[qb + r * 8 + g] = rs[r];
    }
    __syncthreads();
    g_rinv[(size_t)bh * SEQ + q0 + tid] = 1.0f / srow[tid];
}

// ---------------------------------------------------------------------------
// K2: tensor-core attention, TQ=256; K/V frags shared across two q-sets;
// attn written NORMALIZED; ctx as bf16 hi/lo.
// ---------------------------------------------------------------------------
__global__ __launch_bounds__(256, 2) void attn_mma(float* __restrict__ attn)
{
    extern __shared__ __nv_bfloat16 smb[];
    uint32_t* mw = (uint32_t*)(smb + SMEM_BF16);   // [3][256][2] words

    const int tid  = threadIdx.x;
    const int w    = tid >> 5;
    const int lane = tid & 31;
    const int g    = lane >> 2;
    const int tig  = lane & 3;
    const int qb   = w * 32;

    const int bh = blockIdx.y;
    const int b = bh >> 2, h = bh & 3;
    const int q0 = blockIdx.x * TQ;
    const float CE = 1.4426950408889634f * 0.17677669529663689f;
    const size_t bS = (size_t)b * SEQ;

    const int kj   = tid >> 2;
    const int kseg = (tid & 3) * 8;
    const int vv   = tid >> 3;
    const int vseg = (tid & 7) * 8;
    const __nv_bfloat16* gK_h = g_Kh + bS * DM + h * 32;
    const __nv_bfloat16* gK_l = g_Kl + bS * DM + h * 32;
    const __nv_bfloat16* gV_t = g_Vt + ((size_t)bh * 32 + vv) * SEQ;
    const uint32_t* gMB = g_mbits + (bS + q0) * SW;

    auto issue_chunk = [&](int kc) {
        __nv_bfloat16* kh = smb + (kc % 3) * BUF_SZ;
        __nv_bfloat16* kl = kh + 64 * QSTR;
        __nv_bfloat16* vh = kl + 64 * QSTR;
        size_t koff = (size_t)(kc * TK + kj) * DM + kseg;
        cp16(kh + kj * QSTR + kseg, gK_h + koff);
        cp16(kl + kj * QSTR + kseg, gK_l + koff);
        cp16(vh + vv * ESTR + vseg, gV_t + kc * TK + vseg);
        cp8(mw + (kc % 3) * 512 + tid * 2, gMB + (size_t)tid * SW + kc * 2);
    };

    issue_chunk(0);
    cp_commit();
    issue_chunk(1);
    cp_commit();

    // Q fragments for 2 q-sets
    uint32_t qh[2][2][4], ql[2][2][4];
    {
        const __nv_bfloat16* gQ_h = g_Qh + (bS + q0) * DM + h * 32;
        const __nv_bfloat16* gQ_l = g_Ql + (bS + q0) * DM + h * 32;
#pragma unroll
        for (int qs = 0; qs < 2; qs++)
#pragma unroll
            for (int kk = 0; kk < 2; kk++) {
                int c0 = kk * 16 + tig * 2;
                size_t r0o = (size_t)(qb + qs * 16 + g) * DM + c0;
                size_t r1o = r0o + 8 * DM;
                qh[qs][kk][0] = *(const uint32_t*)&gQ_h[r0o];
                qh[qs][kk][1] = *(const uint32_t*)&gQ_h[r1o];
                qh[qs][kk][2] = *(const uint32_t*)&gQ_h[r0o + 8];
                qh[qs][kk][3] = *(const uint32_t*)&gQ_h[r1o + 8];
                ql[qs][kk][0] = *(const uint32_t*)&gQ_l[r0o];
                ql[qs][kk][1] = *(const uint32_t*)&gQ_l[r1o];
                ql[qs][kk][2] = *(const uint32_t*)&gQ_l[r0o + 8];
                ql[qs][kk][3] = *(const uint32_t*)&gQ_l[r1o + 8];
            }
    }

    const int qg0 = q0 + qb + g;
    float rinv[4];
#pragma unroll
    for (int r = 0; r < 4; r++)
        rinv[r] = g_rinv[(size_t)bh * SEQ + qg0 + r * 8];

    float cacc[2][4][4];
#pragma unroll
    for (int qs = 0; qs < 2; qs++)
#pragma unroll
        for (int n = 0; n < 4; n++)
#pragma unroll
            for (int i = 0; i < 4; i++) cacc[qs][n][i] = 0.f;

    const size_t arow = ((size_t)bh * SEQ + qg0) * SEQ;   // + r*8*SEQ

    for (int kc = 0; kc < NC; kc++) {
        const int k0 = kc * TK;

        cp_wait<1>();
        __syncthreads();
        if (kc + 2 < NC) issue_chunk(kc + 2);
        cp_commit();

        const __nv_bfloat16* kh = smb + (kc % 3) * BUF_SZ;
        const __nv_bfloat16* kl = kh + 64 * QSTR;
        const __nv_bfloat16* vh = kl + 64 * QSTR;
        uint2 mwq[4];
#pragma unroll
        for (int r = 0; r < 4; r++)
            mwq[r] = *(const uint2*)&mw[(kc % 3) * 512 + (qb + r * 8 + g) * 2];

#pragma unroll
        for (int jj = 0; jj < 4; jj++) {
            uint32_t eh[2][2][2];   // [qset][s][row01]
#pragma unroll
            for (int s = 0; s < 2; s++) {
                const int j0 = jj * 16 + s * 8;
                const int dof0 = tig * 2;
                const int dof1 = 16 + tig * 2;
                uint32_t kh00 = *(const uint32_t*)&kh[(j0 + g) * QSTR + dof0];
                uint32_t kh01 = *(const uint32_t*)&kh[(j0 + g) * QSTR + dof0 + 8];
                uint32_t kl00 = *(const uint32_t*)&kl[(j0 + g) * QSTR + dof0];
                uint32_t kl01 = *(const uint32_t*)&kl[(j0 + g) * QSTR + dof0 + 8];
                uint32_t kh10 = *(const uint32_t*)&kh[(j0 + g) * QSTR + dof1];
                uint32_t kh11 = *(const uint32_t*)&kh[(j0 + g) * QSTR + dof1 + 8];
                uint32_t kl10 = *(const uint32_t*)&kl[(j0 + g) * QSTR + dof1];
                uint32_t kl11 = *(const uint32_t*)&kl[(j0 + g) * QSTR + dof1 + 8];
                const int jgl = k0 + j0 + tig * 2;
                const int bp = ((jj & 1) * 16 + s * 8 + tig * 2);
#pragma unroll
                for (int qs = 0; qs < 2; qs++) {
                    float c[4]  = {0.f, 0.f, 0.f, 0.f};
                    float c2[4] = {0.f, 0.f, 0.f, 0.f};
                    mma16816(c, qh[qs][0][0], qh[qs][0][1], qh[qs][0][2], qh[qs][0][3], kh00, kh01);
                    mma16816(c, qh[qs][0][0], qh[qs][0][1], qh[qs][0][2], qh[qs][0][3], kl00, kl01);
                    mma16816(c, ql[qs][0][0], ql[qs][0][1], ql[qs][0][2], ql[qs][0][3], kh00, kh01);
                    mma16816(c2, qh[qs][1][0], qh[qs][1][1], qh[qs][1][2], qh[qs][1][3], kh10, kh11);
                    mma16816(c2, qh[qs][1][0], qh[qs][1][1], qh[qs][1][2], qh[qs][1][3], kl10, kl11);
                    mma16816(c2, ql[qs][1][0], ql[qs][1][1], ql[qs][1][2], ql[qs][1][3], kh10, kh11);
#pragma unroll
                    for (int i = 0; i < 4; i++) c[i] += c2[i];

                    const uint32_t w0 = (jj < 2) ? mwq[qs * 2].x : mwq[qs * 2].y;
                    const uint32_t w1 = (jj < 2) ? mwq[qs * 2 + 1].x : mwq[qs * 2 + 1].y;
                    float e00 = ((w0 >> bp) & 1)       ? 0.f : ex2(c[0] * CE) * rinv[qs * 2];
                    float e01 = ((w0 >> (bp + 1)) & 1) ? 0.f : ex2(c[1] * CE) * rinv[qs * 2];
                    float e10 = ((w1 >> bp) & 1)       ? 0.f : ex2(c[2] * CE) * rinv[qs * 2 + 1];
                    float e11 = ((w1 >> (bp + 1)) & 1) ? 0.f : ex2(c[3] * CE) * rinv[qs * 2 + 1];
                    *(float2*)(attn + arow + (size_t)(qs * 16) * SEQ + jgl) = make_float2(e00, e01);
                    *(float2*)(attn + arow + (size_t)(qs * 16 + 8) * SEQ + jgl) = make_float2(e10, e11);
                    eh[qs][s][0] = pack_bf16x2(e00, e01);
                    eh[qs][s][1] = pack_bf16x2(e10, e11);
                }
            }
            const int c0 = jj * 16 + tig * 2;
#pragma unroll
            for (int nt2 = 0; nt2 < 4; nt2++) {
                int v0 = nt2 * 8;
                uint32_t vb0 = *(const uint32_t*)&vh[(v0 + g) * ESTR + c0];
                uint32_t vb1 = *(const uint32_t*)&vh[(v0 + g) * ESTR + c0 + 8];
                mma16816(cacc[0][nt2], eh[0][0][0], eh[0][0][1], eh[0][1][0], eh[0][1][1], vb0, vb1);
                mma16816(cacc[1][nt2], eh[1][0][0], eh[1][0][1], eh[1][1][0], eh[1][1][1], vb0, vb1);
            }
        }
    }

    // ---- ctx write as bf16 hi/lo ----
#pragma unroll
    for (int qs = 0; qs < 2; qs++) {
        size_t row0 = (bS + qg0 + qs * 16) * (size_t)DM + h * 32;
        size_t row1 = row0 + 8 * DM;
#pragma unroll
        for (int nt = 0; nt < 4; nt++) {
            int v = nt * 8 + tig * 2;
#pragma unroll
            for (int rr = 0; rr < 2; rr++) {
                float f0 = cacc[qs][nt][rr * 2], f1 = cacc[qs][nt][rr * 2 + 1];
                uint32_t h0 = bf16_rn_bits(f0), h1 = bf16_rn_bits(f1);
                float l0 = f0 - __uint_as_float(h0 << 16);
                float l1 = f1 - __uint_as_float(h1 << 16);
                size_t off = (rr ? row1 : row0) + v;
                *(uint32_t*)&g_Ch[off] = h0 | (h1 << 16);
                *(uint32_t*)&g_Cl[off] = bf16_rn_bits(l0) | (bf16_rn_bits(l1) << 16);
            }
        }
    }
}

// ---------------------------------------------------------------------------
// K4: out = LayerNorm(ctx @ W_fc + g_R), tensor-core (unchanged).
// ---------------------------------------------------------------------------
__global__ __launch_bounds__(256) void out_ln_tc(const float* __restrict__ gamma,
                                                 const float* __restrict__ beta,
                                                 float* __restrict__ out)
{
    extern __shared__ __nv_bfloat16 psm[];
    __nv_bfloat16* sAh  = psm + PA_H;
    __nv_bfloat16* sAl  = psm + PA_L;
    __nv_bfloat16* sWth = psm + PW_H;
    __nv_bfloat16* sWtl = psm + PW_L;

    const int tid  = threadIdx.x;
    const int w    = tid >> 5;
    const int lane = tid & 31;
    const int g    = lane >> 2;
    const int tig  = lane & 3;
    const int r0   = blockIdx.x * 64;

    const __nv_bfloat16* gWh = g_Wth + 4 * DM * DM;
    const __nv_bfloat16* gWl = g_Wtl + 4 * DM * DM;

    const int mt = w >> 1;
    const int nh = (w & 1) * 64;
    const int m0 = mt * 16 + g;
    const int m1 = m0 + 8;

    float acc[8][4];
#pragma unroll
    for (int nt = 0; nt < 8; nt++)
#pragma unroll
        for (int i = 0; i < 4; i++) acc[nt][i] = 0.f;

    for (int ks = 0; ks < 2; ks++) {
        if (ks) __syncthreads();
        {
#pragma unroll
            for (int it = 0; it < 2; it++) {
                int id = tid + it * 256;
                int row = id >> 3, seg = (id & 7) * 8;
                size_t src = (size_t)(r0 + row) * DM + ks * 64 + seg;
                cp16(sAh + row * PSTR + seg, g_Ch + src);
                cp16(sAl + row * PSTR + seg, g_Cl + src);
            }
#pragma unroll
            for (int it = 0; it < 4; it++) {
                int id = tid + it * 256;
                int n = id >> 3, seg = (id & 7) * 8;
                size_t src = (size_t)n * DM + ks * 64 + seg;
                cp16(sWth + n * PSTR + seg, gWh + src);
                cp16(sWtl + n * PSTR + seg, gWl + src);
            }
        }
        cp_commit();
        cp_wait<0>();
        __syncthreads();

#pragma unroll
        for (int kk = 0; kk < 64; kk += 16) {
            const int dof = kk + tig * 2;
            uint32_t ah0 = *(const uint32_t*)&sAh[m0 * PSTR + dof];
            uint32_t ah1 = *(const uint32_t*)&sAh[m1 * PSTR + dof];
            uint32_t ah2 = *(const uint32_t*)&sAh[m0 * PSTR + dof + 8];
            uint32_t ah3 = *(const uint32_t*)&sAh[m1 * PSTR + dof + 8];
            uint32_t al0 = *(const uint32_t*)&sAl[m0 * PSTR + dof];
            uint32_t al1 = *(const uint32_t*)&sAl[m1 * PSTR + dof];
            uint32_t al2 = *(const uint32_t*)&sAl[m0 * PSTR + dof + 8];
            uint32_t al3 = *(const uint32_t*)&sAl[m1 * PSTR + dof + 8];
#pragma unroll
            for (int nt = 0; nt < 8; nt++) {
                int ncol = nh + nt * 8 + g;
                uint32_t bh0 = *(const uint32_t*)&sWth[ncol * PSTR + dof];
                uint32_t bh1 = *(const uint32_t*)&sWth[ncol * PSTR + dof + 8];
                uint32_t bl0 = *(const uint32_t*)&sWtl[ncol * PSTR + dof];
                uint32_t bl1 = *(const uint32_t*)&sWtl[ncol * PSTR + dof + 8];
                mma16816(acc[nt], ah0, ah1, ah2, ah3, bh0, bh1);
                mma16816(acc[nt], ah0, ah1, ah2, ah3, bl0, bl1);
                mma16816(acc[nt], al0, al1, al2, al3, bh0, bh1);
            }
        }
    }

    const size_t row0 = (size_t)(r0 + m0);
    const size_t row1 = row0 + 8;
    float ps0 = 0.f, pq0 = 0.f, ps1 = 0.f, pq1 = 0.f;
#pragma unroll
    for (int nt = 0; nt < 8; nt++) {
        int col = nh + nt * 8 + tig * 2;
        float2 rv0 = *(const float2*)&g_R[row0 * DM + col];
        float2 rv1 = *(const float2*)&g_R[row1 * DM + col];
        acc[nt][0] += rv0.x; acc[nt][1] += rv0.y;
        acc[nt][2] += rv1.x; acc[nt][3] += rv1.y;
        ps0 += acc[nt][0] + acc[nt][1];
        pq0 += acc[nt][0] * acc[nt][0] + acc[nt][1] * acc[nt][1];
        ps1 += acc[nt][2] + acc[nt][3];
        pq1 += acc[nt][2] * acc[nt][2] + acc[nt][3] * acc[nt][3];
    }

    float* red1 = (float*)psm;
    float* red2 = red1 + 64 * 8;
    float* smu  = red2 + 64 * 8;
    float* srs  = smu + 64;
    __syncthreads();
    const int slot = (w & 1) * 4 + tig;
    red1[m0 * 8 + slot] = ps0;
    red2[m0 * 8 + slot] = pq0;
    red1[m1 * 8 + slot] = ps1;
    red2[m1 * 8 + slot] = pq1;
    __syncthreads();
    if (tid < 64) {
        float s = 0.f, q = 0.f;
#pragma unroll
        for (int j = 0; j < 8; j++) { s += red1[tid * 8 + j]; q += red2[tid * 8 + j]; }
        float mu = s * (1.0f / 128.0f);
        float var = q * (1.0f / 128.0f) - mu * mu;
        smu[tid] = mu;
        srs[tid] = rsqrtf(var + 1e-5f);
    }
    __syncthreads();

    const float mu0 = smu[m0], rs0 = srs[m0];
    const float mu1 = smu[m1], rs1 = srs[m1];
#pragma unroll
    for (int nt = 0; nt < 8; nt++) {
        int col = nh + nt * 8 + tig * 2;
        float2 gm = *(const float2*)&gamma[col];
        float2 bt = *(const float2*)&beta[col];
        float2 o0 = make_float2((acc[nt][0] - mu0) * rs0 * gm.x + bt.x,
                                (acc[nt][1] - mu0) * rs0 * gm.y + bt.y);
        float2 o1 = make_float2((acc[nt][2] - mu1) * rs1 * gm.x + bt.x,
                                (acc[nt][3] - mu1) * rs1 * gm.y + bt.y);
        *(float2*)&out[row0 * DM + col] = o0;
        *(float2*)&out[row1 * DM + col] = o1;
    }
}

// ---------------------------------------------------------------------------
extern "C" void kernel_launch(void* const* d_in, const int* in_sizes, int n_in,
                              void* d_out, int out_size)
{
    const float* inQ  = (const float*)d_in[0];
    const float* inK  = (const float*)d_in[1];
    const float* inV  = (const float*)d_in[2];
    const unsigned char* mask = (const unsigned char*)d_in[3];
    const float* Wfc0 = (const float*)d_in[4];
    const float* WQ   = (const float*)d_in[5];
    const float* WK   = (const float*)d_in[6];
    const float* WV   = (const float*)d_in[7];
    const float* Wfc  = (const float*)d_in[8];
    const float* gam  = (const float*)d_in[9];
    const float* bet  = (const float*)d_in[10];
    float* out  = (float*)d_out;
    float* attn = out + OUT_ELEMS;

    detect_mask<<<1, 256>>>(mask);                                  // 1
    pack_mask<<<(unsigned)((size_t)BATCH * SEQ * SW / 256), 256>>>(mask);  // 2
    split_inputs<<<dim3(NR * DM / 1024, 3), 256>>>(inQ, inK, inV);  // 3
    split_weights<<<dim3(8, 5), 256>>>(Wfc0, WQ, WK, WV, Wfc);      // 4

    cudaFuncSetAttribute(proj_tc, cudaFuncAttributeMaxDynamicSharedMemorySize,
                         (int)P_SMEM_BYTES);
    proj_tc<<<dim3(NR / 64, 4), 256, P_SMEM_BYTES>>>();             // 5

    dim3 agrid(SEQ / TQ, BATCH * 4);
    cudaFuncSetAttribute(rowsum_pass, cudaFuncAttributeMaxDynamicSharedMemorySize,
                         (int)RS_SMEM_BYTES);
    rowsum_pass<<<agrid, 256, RS_SMEM_BYTES>>>();                   // 6 (ncu)

    cudaFuncSetAttribute(attn_mma, cudaFuncAttributeMaxDynamicSharedMemorySize,
                         (int)SMEM_BYTES);
    attn_mma<<<agrid, 256, SMEM_BYTES>>>(attn);                     // 7

    cudaFuncSetAttribute(out_ln_tc, cudaFuncAttributeMaxDynamicSharedMemorySize,
                         (int)P_SMEM_BYTES);
    out_ln_tc<<<NR / 64, 256, P_SMEM_BYTES>>>(gam, bet, out);       // 8
}